// round 13
// baseline (speedup 1.0000x reference)
#include <cuda_runtime.h>
#include <cuda_bf16.h>
#include <math.h>
#include <stdint.h>

// Problem constants
#define BATCH   4096
#define HID     1024
#define EMBD    64
#define KDIM    1088          // EMBD + HID (W layout only; X holds h only)
#define NOBS    8
#define NSTEPS  19
#define GROWS   4096          // 4*HID gate rows

// GEMM tiling
#define TM      128           // batch rows per CTA
#define TN      128           // permuted gate cols per CTA = 32 hidden units x 4 gates
#define TKC     32            // K chunk (32 bf16 = 64B rows -> SW64 swizzle)
#define NCHUNK  34            // 2 emb chunks (smem-computed) + 32 h chunks

// smem: 2 stages x 4 tiles (Ahi, Alo, Whi, Wlo) x 8KB = 64KB
// gbuf (128 x 132 floats = 67584B) overlays the stage buffers after the GEMM.
#define STAGE_B 32768
#define T_AHI   0
#define T_ALO   8192
#define T_WHI   16384
#define T_WLO   24576
#define GB_STRIDE 132
#define SBIAS   67584         // 512B: permuted gate bias
#define SOUT01  68096         // 1024B: out[s-1][:,0:2] for this CTA's 128 rows
#define SMEM_BYTES (68096 + 1024 + 1024)

// ---------------- device state (allocation-free scratch) ----------------
// h double-buffered by STEP PARITY (race-free across CTAs/waves).
__device__ __nv_bfloat16 g_Xh[2][BATCH * HID];    // h hi
__device__ __nv_bfloat16 g_Xl[2][BATCH * HID];    // h lo residual
__device__ __nv_bfloat16 g_Wphi[GROWS * KDIM];    // permuted [W_ih|W_hh] hi
__device__ __nv_bfloat16 g_Wplo[GROWS * KDIM];    // lo residual
__device__ float         g_bp[GROWS];             // permuted b_ih+b_hh
__device__ float         g_c[BATCH * HID];        // cell state (fp32)
__device__ float         g_osc[32][5][BATCH];     // out_proj partials [bn][o][row]

// ---------------- helpers ----------------
__device__ __forceinline__ uint32_t smem_u32(const void* p) {
    uint32_t a;
    asm("{ .reg .u64 t; cvta.to.shared.u64 t, %1; cvt.u32.u64 %0, t; }" : "=r"(a) : "l"(p));
    return a;
}
__device__ __forceinline__ void cp16(uint32_t dst, const void* src) {
    asm volatile("cp.async.cg.shared.global [%0], [%1], 16;" :: "r"(dst), "l"(src));
}
#define CP_COMMIT() asm volatile("cp.async.commit_group;" ::: "memory")
__device__ __forceinline__ uint32_t swz64(uint32_t off) { return off ^ ((off >> 3) & 0x30); }
__device__ __forceinline__ void sts32(uint32_t addr, uint32_t v) {
    asm volatile("st.shared.b32 [%0], %1;" :: "r"(addr), "r"(v));
}
__device__ __forceinline__ void ldmat4(uint32_t* r, uint32_t addr) {
    asm volatile("ldmatrix.sync.aligned.m8n8.x4.shared.b16 {%0,%1,%2,%3}, [%4];"
        : "=r"(r[0]), "=r"(r[1]), "=r"(r[2]), "=r"(r[3]) : "r"(addr));
}
__device__ __forceinline__ void mma16816(float* c, const uint32_t* a, uint32_t b0, uint32_t b1) {
    asm volatile("mma.sync.aligned.m16n8k16.row.col.f32.bf16.bf16.f32 "
        "{%0,%1,%2,%3}, {%4,%5,%6,%7}, {%8,%9}, {%0,%1,%2,%3};"
        : "+f"(c[0]), "+f"(c[1]), "+f"(c[2]), "+f"(c[3])
        : "r"(a[0]), "r"(a[1]), "r"(a[2]), "r"(a[3]), "r"(b0), "r"(b1));
}

__device__ __forceinline__ float sigf(float x) {
    return __fdividef(1.0f, 1.0f + __expf(-x));
}
__device__ __forceinline__ float tanh_f(float x) {
    return fmaf(2.0f, sigf(2.0f * x), -1.0f);
}

// Load one K-chunk stage. W always; A (h) only for chunks >= 2 (chunks 0/1 are
// the smem-computed embedding).
__device__ __forceinline__ void load_chunk(uint32_t stage,
                                           const __nv_bfloat16* __restrict__ Xhi,
                                           const __nv_bfloat16* __restrict__ Xlo,
                                           int bm, int bn, int ch, int tid)
{
    const int r = tid >> 2, q = tid & 3;           // 64 rows x 4 16B-quads per pass
    const int kw = ch * TKC;                       // W K-offset (KDIM-wide)
    const int ka = kw - EMBD;                      // A K-offset (HID-wide)
    const bool la = (ch >= 2);
    #pragma unroll
    for (int u = 0; u < 2; ++u) {                  // 2 x 64 rows = 128 rows
        const int row = r + u * 64;
        const uint32_t o = swz64((uint32_t)(row * 64 + q * 16));
        if (la) {
            const size_t ar = (size_t)(bm * TM + row) * HID + ka + q * 8;
            cp16(stage + T_AHI + o, Xhi + ar);
            cp16(stage + T_ALO + o, Xlo + ar);
        }
        const size_t br = (size_t)(bn * TN + row) * KDIM + kw + q * 8;
        cp16(stage + T_WHI + o, g_Wphi + br);
        cp16(stage + T_WLO + o, g_Wplo + br);
    }
    CP_COMMIT();
}

// ---------------- one-time prep: permute+split W, combine biases ----------------
extern "C" __global__ void __launch_bounds__(256)
prep_kernel(const float* __restrict__ W_ih, const float* __restrict__ b_ih,
            const float* __restrict__ W_hh, const float* __restrict__ b_hh)
{
    int idx = blockIdx.x * 256 + threadIdx.x;       // 0 .. GROWS*KDIM
    int ro = idx / KDIM, k = idx - ro * KDIM;
    int j = ro >> 2, q = ro & 3;                    // ro = j*4 + gate
    int orig = q * HID + j;
    float v = (k < EMBD) ? W_ih[(size_t)orig * EMBD + k]
                         : W_hh[(size_t)orig * HID + (k - EMBD)];
    __nv_bfloat16 hi = __float2bfloat16(v);
    g_Wphi[idx] = hi;
    g_Wplo[idx] = __float2bfloat16(v - __bfloat162float(hi));
    if (k == 0) g_bp[ro] = b_ih[orig] + b_hh[orig];
}

// ---------------- fused per-step kernel ----------------
// prologue: reduce out[s-1] partials (d_out write + predictive feedback) + emb
// mainloop: 3-pass split-bf16 gates GEMM (mma.sync, chunk-major)
// epilogue: LSTM cell update + h hi/lo store + out_proj partials to scratch
extern "C" __global__ void __launch_bounds__(256, 2)
gates_kernel(const float* __restrict__ observed,
             const float* __restrict__ W_emb, const float* __restrict__ b_emb,
             const float* __restrict__ W_out, const float* __restrict__ b_out,
             float* __restrict__ out, int s)
{
    extern __shared__ char smraw[];
    const uint32_t sm0  = smem_u32(smraw);
    const uint32_t base = (sm0 + 1023) & ~1023u;
    const uint32_t pad  = base - sm0;
    const uint32_t Soff[2] = {base, base + STAGE_B};

    const int tid  = threadIdx.x;
    const int wid  = tid >> 5;
    const int lane = tid & 31;
    const int wm   = wid >> 2;      // 0..1 : warp M position (64 rows each)
    const int wn   = wid & 3;       // 0..3 : warp N position (32 cols each)
    const int bn   = blockIdx.x;    // 0..31 (permuted gate-col tile)
    const int bm   = blockIdx.y;    // 0..31 (batch tile)

    const __nv_bfloat16* Xhi_r = g_Xh[s & 1];
    const __nv_bfloat16* Xlo_r = g_Xl[s & 1];
    __nv_bfloat16* Xhi_w = g_Xh[(s + 1) & 1];
    __nv_bfloat16* Xlo_w = g_Xl[(s + 1) & 1];

    // kick off W chunk 0 ASAP (no A cp.async for chunks 0/1)
    load_chunk(Soff[0], Xhi_r, Xlo_r, bm, bn, 0, tid);

    float* bias_s = (float*)(smraw + pad + SBIAS);
    if (tid < TN) bias_s[tid] = g_bp[bn * TN + tid];

    // ---- prologue A: finish out[s-1] (scratch partial reduction) ----
    float* out01 = (float*)(smraw + pad + SOUT01);
    if (s > 0) {
        if (s >= NOBS || bn == 0) {
            const int r_lo = tid & 127, o_sel = tid >> 7;   // (row, o in {0,1})
            const int grow = bm * TM + r_lo;
            float a_ = b_out[o_sel];
            #pragma unroll 8
            for (int q2 = 0; q2 < 32; ++q2) a_ += g_osc[q2][o_sel][grow];
            out01[o_sel * 128 + r_lo] = a_;
            if (bn == 0) {
                out[(size_t)(s - 1) * BATCH * 5 + (size_t)grow * 5 + o_sel] = a_;
                if (tid < 128) {
                    #pragma unroll
                    for (int o2 = 2; o2 < 5; ++o2) {
                        float b_ = b_out[o2];
                        #pragma unroll 8
                        for (int q2 = 0; q2 < 32; ++q2) b_ += g_osc[q2][o2][grow];
                        out[(size_t)(s - 1) * BATCH * 5 + (size_t)grow * 5 + o2] = b_;
                    }
                }
            }
        }
        __syncthreads();
    }

    // ---- prologue B: embedding -> swizzled A slots of stages 0 (e<32) / 1 (e>=32) ----
    {
        const int rloc = tid >> 1, eh = tid & 1;
        const int grow = bm * TM + rloc;
        float d0, d1;
        if (s < NOBS) {
            const float* o1 = observed + (size_t)(s + 1) * BATCH * 2 + (size_t)grow * 2;
            const float* o0 = observed + (size_t)s       * BATCH * 2 + (size_t)grow * 2;
            d0 = o1[0] - o0[0];
            d1 = o1[1] - o0[1];
        } else {
            d0 = out01[rloc];
            d1 = out01[128 + rloc];
        }
        const uint32_t ahi = Soff[eh] + T_AHI;
        const uint32_t alo = Soff[eh] + T_ALO;
        #pragma unroll
        for (int p = 0; p < 16; ++p) {
            const int e0 = eh * 32 + p * 2;
            float v0 = fmaxf(fmaf(W_emb[e0 * 2],     d0,
                           fmaf(W_emb[e0 * 2 + 1], d1, b_emb[e0])), 0.0f);
            float v1 = fmaxf(fmaf(W_emb[e0 * 2 + 2], d0,
                           fmaf(W_emb[e0 * 2 + 3], d1, b_emb[e0 + 1])), 0.0f);
            __nv_bfloat16 h0 = __float2bfloat16(v0), h1 = __float2bfloat16(v1);
            uint32_t whi = (uint32_t)__bfloat16_as_ushort(h0)
                         | ((uint32_t)__bfloat16_as_ushort(h1) << 16);
            uint32_t wlo = (uint32_t)__bfloat16_as_ushort(__float2bfloat16(v0 - __bfloat162float(h0)))
                         | ((uint32_t)__bfloat16_as_ushort(__float2bfloat16(v1 - __bfloat162float(h1))) << 16);
            const uint32_t o = swz64((uint32_t)(rloc * 64 + p * 4));
            sts32(ahi + o, whi);
            sts32(alo + o, wlo);
        }
    }

    // ---- mainloop: chunk-major, 3 products per chunk ----
    float acc[4][4][4];
    #pragma unroll
    for (int mt = 0; mt < 4; ++mt)
        #pragma unroll
        for (int nt = 0; nt < 4; ++nt)
            #pragma unroll
            for (int v = 0; v < 4; ++v) acc[mt][nt][v] = 0.0f;

    const int niter = (s == 0) ? 2 : NCHUNK;   // step 0: h==0, emb chunks only
    const int lrow  = lane & 15;
    const int lhalf = (lane >> 4) * 16;

    for (int it = 0; it < niter; ++it) {
        const int b = it & 1, nb = b ^ 1;
        if (it + 1 < niter) {
            load_chunk(Soff[nb], Xhi_r, Xlo_r, bm, bn, it + 1, tid);
            asm volatile("cp.async.wait_group 1;" ::: "memory");
        } else {
            asm volatile("cp.async.wait_group 0;" ::: "memory");
        }
        __syncthreads();

        const uint32_t st = Soff[b];
        #pragma unroll
        for (int kk = 0; kk < 2; ++kk) {
            uint32_t bhi[2][4], blo[2][4];
            #pragma unroll
            for (int nt2 = 0; nt2 < 2; ++nt2) {
                const uint32_t boff = swz64((uint32_t)((wn * 32 + nt2 * 16 + lrow) * 64 + kk * 32 + lhalf));
                ldmat4(bhi[nt2], st + T_WHI + boff);
                ldmat4(blo[nt2], st + T_WLO + boff);
            }
            #pragma unroll
            for (int mt = 0; mt < 4; ++mt) {
                const uint32_t aoff = swz64((uint32_t)((wm * 64 + mt * 16 + lrow) * 64 + kk * 32 + lhalf));
                uint32_t ahi[4], alo[4];
                ldmat4(ahi, st + T_AHI + aoff);
                ldmat4(alo, st + T_ALO + aoff);
                #pragma unroll
                for (int nt = 0; nt < 4; ++nt) {
                    const uint32_t* bf = bhi[nt >> 1];
                    uint32_t b0 = (nt & 1) ? bf[1] : bf[0];
                    uint32_t b1 = (nt & 1) ? bf[3] : bf[2];
                    mma16816(acc[mt][nt], ahi, b0, b1);
                    mma16816(acc[mt][nt], alo, b0, b1);
                    const uint32_t* bl = blo[nt >> 1];
                    uint32_t c0 = (nt & 1) ? bl[1] : bl[0];
                    uint32_t c1 = (nt & 1) ? bl[3] : bl[2];
                    mma16816(acc[mt][nt], ahi, c0, c1);
                }
            }
        }
        __syncthreads();
    }

    // ------- dump accumulators to smem (gbuf overlays stage buffers) -------
    float* gbuf = (float*)(smraw + pad);
    #pragma unroll
    for (int mt = 0; mt < 4; ++mt)
        #pragma unroll
        for (int nt = 0; nt < 4; ++nt) {
            int r0 = wm * 64 + mt * 16 + (lane >> 2);
            int c  = wn * 32 + nt * 8 + (lane & 3) * 2;
            *(float2*)&gbuf[r0 * GB_STRIDE + c]       = make_float2(acc[mt][nt][0], acc[mt][nt][1]);
            *(float2*)&gbuf[(r0 + 8) * GB_STRIDE + c] = make_float2(acc[mt][nt][2], acc[mt][nt][3]);
        }
    __syncthreads();

    // ------- epilogue: LSTM cell + h store + out_proj partials -------
    float wo[5];
    #pragma unroll
    for (int o = 0; o < 5; ++o) wo[o] = W_out[o * HID + bn * 32 + lane];

    #pragma unroll 1
    for (int u = 0; u < 16; ++u) {
        int idx = tid + 256 * u;       // warp wid handles m = wid + 8u, j = lane
        int m = idx >> 5, j = idx & 31;
        int row = bm * TM + m;
        int jglob = bn * 32 + j;
        const float* gp = &gbuf[m * GB_STRIDE + j * 4];
        float gi = gp[0] + bias_s[j * 4 + 0];
        float gf = gp[1] + bias_s[j * 4 + 1];
        float gg = gp[2] + bias_s[j * 4 + 2];
        float go = gp[3] + bias_s[j * 4 + 3];
        float xi = sigf(gi), xf = sigf(gf);
        float xg = tanh_f(gg), xo = sigf(go);
        size_t ci = (size_t)row * HID + jglob;
        float cold = (s > 0) ? g_c[ci] : 0.0f;
        float cn = fmaf(xf, cold, xi * xg);
        g_c[ci] = cn;
        float hn = xo * tanh_f(cn);
        __nv_bfloat16 hb = __float2bfloat16(hn);
        Xhi_w[ci] = hb;
        Xlo_w[ci] = __float2bfloat16(hn - __bfloat162float(hb));
        // out_proj partials for this CTA's 32 h-cols (warp-reduce over j = lane)
        #pragma unroll
        for (int o = 0; o < 5; ++o) {
            float p = hn * wo[o];
            p += __shfl_xor_sync(0xffffffff, p, 16);
            p += __shfl_xor_sync(0xffffffff, p, 8);
            p += __shfl_xor_sync(0xffffffff, p, 4);
            p += __shfl_xor_sync(0xffffffff, p, 2);
            p += __shfl_xor_sync(0xffffffff, p, 1);
            if (lane == 0) g_osc[bn][o][row] = p;
        }
    }
}

// ---------------- final output row: reduce scratch partials for step 18 ----------------
extern "C" __global__ void __launch_bounds__(256)
reduce_out_kernel(const float* __restrict__ b_out, float* __restrict__ out, int s)
{
    int row = blockIdx.x * 256 + threadIdx.x;   // 0..4095
    #pragma unroll
    for (int o = 0; o < 5; ++o) {
        float a = b_out[o];
        #pragma unroll 8
        for (int q = 0; q < 32; ++q) a += g_osc[q][o][row];
        out[(size_t)s * BATCH * 5 + (size_t)row * 5 + o] = a;
    }
}

extern "C" void kernel_launch(void* const* d_in, const int* in_sizes, int n_in,
                              void* d_out, int out_size)
{
    const float* observed = (const float*)d_in[0];
    const float* W_emb    = (const float*)d_in[1];
    const float* b_emb    = (const float*)d_in[2];
    const float* W_ih     = (const float*)d_in[3];
    const float* b_ih     = (const float*)d_in[4];
    const float* W_hh     = (const float*)d_in[5];
    const float* b_hh     = (const float*)d_in[6];
    const float* W_out    = (const float*)d_in[7];
    const float* b_out    = (const float*)d_in[8];
    float* out = (float*)d_out;

    cudaFuncSetAttribute(gates_kernel, cudaFuncAttributeMaxDynamicSharedMemorySize, SMEM_BYTES);

    prep_kernel<<<(GROWS * KDIM) / 256, 256>>>(W_ih, b_ih, W_hh, b_hh);

    dim3 grid(GROWS / TN, BATCH / TM);   // (32, 32)
    for (int s = 0; s < NSTEPS; ++s) {
        gates_kernel<<<grid, 256, SMEM_BYTES>>>(observed, W_emb, b_emb,
                                                W_out, b_out, out, s);
    }
    reduce_out_kernel<<<BATCH / 256, 256>>>(b_out, out, NSTEPS - 1);
}

// round 14
// speedup vs baseline: 1.0230x; 1.0230x over previous
#include <cuda_runtime.h>
#include <cuda_bf16.h>
#include <math.h>
#include <stdint.h>

// Problem constants
#define BATCH   4096
#define HID     1024
#define EMBD    64
#define KDIM    1088          // EMBD + HID (W layout only; X holds h only)
#define NOBS    8
#define NSTEPS  19
#define GROWS   4096          // 4*HID gate rows

// GEMM tiling
#define TM      128           // batch rows per CTA
#define TN      128           // permuted gate cols per CTA = 32 hidden units x 4 gates
#define TKC     32            // K chunk (32 bf16 = 64B rows -> SW64 swizzle)
#define NCHUNK  34            // 2 emb chunks (smem-computed) + 32 h chunks

// smem: 2 stages x 4 tiles (Ahi, Alo, Whi, Wlo) x 8KB = 64KB
// gbuf (128 x 132 floats = 67584B) overlays the stage buffers after the GEMM.
#define STAGE_B 32768
#define T_AHI   0
#define T_ALO   8192
#define T_WHI   16384
#define T_WLO   24576
#define GB_STRIDE 132
#define SBIAS   67584         // 512B: permuted gate bias
#define SOUT01  68096         // 1024B: out[s-1][:,0:2] for this CTA's 128 rows
#define SWOUT   69120         // 640B: W_out[0:5][bn*32 .. bn*32+31]
#define SHBUF   69760         // 16896B: hn staging [128][33] floats
#define HB_STRIDE 33
#define SMEM_BYTES (69760 + 16896 + 1024)

// ---------------- device state (allocation-free scratch) ----------------
// h double-buffered by STEP PARITY (race-free across CTAs/waves).
__device__ __nv_bfloat16 g_Xh[2][BATCH * HID];    // h hi
__device__ __nv_bfloat16 g_Xl[2][BATCH * HID];    // h lo residual
__device__ __nv_bfloat16 g_Wphi[GROWS * KDIM];    // permuted [W_ih|W_hh] hi
__device__ __nv_bfloat16 g_Wplo[GROWS * KDIM];    // lo residual
__device__ float         g_bp[GROWS];             // permuted b_ih+b_hh
__device__ float         g_c[BATCH * HID];        // cell state (fp32)
__device__ float         g_osc[32][5][BATCH];     // out_proj partials [bn][o][row]

// ---------------- helpers ----------------
__device__ __forceinline__ uint32_t smem_u32(const void* p) {
    uint32_t a;
    asm("{ .reg .u64 t; cvta.to.shared.u64 t, %1; cvt.u32.u64 %0, t; }" : "=r"(a) : "l"(p));
    return a;
}
__device__ __forceinline__ void cp16(uint32_t dst, const void* src) {
    asm volatile("cp.async.cg.shared.global [%0], [%1], 16;" :: "r"(dst), "l"(src));
}
#define CP_COMMIT() asm volatile("cp.async.commit_group;" ::: "memory")
__device__ __forceinline__ uint32_t swz64(uint32_t off) { return off ^ ((off >> 3) & 0x30); }
__device__ __forceinline__ void sts32(uint32_t addr, uint32_t v) {
    asm volatile("st.shared.b32 [%0], %1;" :: "r"(addr), "r"(v));
}
__device__ __forceinline__ void ldmat4(uint32_t* r, uint32_t addr) {
    asm volatile("ldmatrix.sync.aligned.m8n8.x4.shared.b16 {%0,%1,%2,%3}, [%4];"
        : "=r"(r[0]), "=r"(r[1]), "=r"(r[2]), "=r"(r[3]) : "r"(addr));
}
__device__ __forceinline__ void mma16816(float* c, const uint32_t* a, uint32_t b0, uint32_t b1) {
    asm volatile("mma.sync.aligned.m16n8k16.row.col.f32.bf16.bf16.f32 "
        "{%0,%1,%2,%3}, {%4,%5,%6,%7}, {%8,%9}, {%0,%1,%2,%3};"
        : "+f"(c[0]), "+f"(c[1]), "+f"(c[2]), "+f"(c[3])
        : "r"(a[0]), "r"(a[1]), "r"(a[2]), "r"(a[3]), "r"(b0), "r"(b1));
}

__device__ __forceinline__ float sigf(float x) {
    return __fdividef(1.0f, 1.0f + __expf(-x));
}
__device__ __forceinline__ float tanh_f(float x) {
    return fmaf(2.0f, sigf(2.0f * x), -1.0f);
}

// Load one K-chunk stage. W always; A (h) only for chunks >= 2 (chunks 0/1 are
// the smem-computed embedding).
__device__ __forceinline__ void load_chunk(uint32_t stage,
                                           const __nv_bfloat16* __restrict__ Xhi,
                                           const __nv_bfloat16* __restrict__ Xlo,
                                           int bm, int bn, int ch, int tid)
{
    const int r = tid >> 2, q = tid & 3;           // 64 rows x 4 16B-quads per pass
    const int kw = ch * TKC;                       // W K-offset (KDIM-wide)
    const int ka = kw - EMBD;                      // A K-offset (HID-wide)
    const bool la = (ch >= 2);
    #pragma unroll
    for (int u = 0; u < 2; ++u) {                  // 2 x 64 rows = 128 rows
        const int row = r + u * 64;
        const uint32_t o = swz64((uint32_t)(row * 64 + q * 16));
        if (la) {
            const size_t ar = (size_t)(bm * TM + row) * HID + ka + q * 8;
            cp16(stage + T_AHI + o, Xhi + ar);
            cp16(stage + T_ALO + o, Xlo + ar);
        }
        const size_t br = (size_t)(bn * TN + row) * KDIM + kw + q * 8;
        cp16(stage + T_WHI + o, g_Wphi + br);
        cp16(stage + T_WLO + o, g_Wplo + br);
    }
    CP_COMMIT();
}

// ---------------- one-time prep: permute+split W, combine biases ----------------
extern "C" __global__ void __launch_bounds__(256)
prep_kernel(const float* __restrict__ W_ih, const float* __restrict__ b_ih,
            const float* __restrict__ W_hh, const float* __restrict__ b_hh)
{
    int idx = blockIdx.x * 256 + threadIdx.x;       // 0 .. GROWS*KDIM
    int ro = idx / KDIM, k = idx - ro * KDIM;
    int j = ro >> 2, q = ro & 3;                    // ro = j*4 + gate
    int orig = q * HID + j;
    float v = (k < EMBD) ? W_ih[(size_t)orig * EMBD + k]
                         : W_hh[(size_t)orig * HID + (k - EMBD)];
    __nv_bfloat16 hi = __float2bfloat16(v);
    g_Wphi[idx] = hi;
    g_Wplo[idx] = __float2bfloat16(v - __bfloat162float(hi));
    if (k == 0) g_bp[ro] = b_ih[orig] + b_hh[orig];
}

// ---------------- fused per-step kernel ----------------
// prologue: reduce out[s-1] partials (d_out write + predictive feedback) + emb
// mainloop: 3-pass split-bf16 gates GEMM (mma.sync, chunk-major)
// epilogue: LSTM cell + h hi/lo store; out_proj partials via smem hbuf (no SHFL)
extern "C" __global__ void __launch_bounds__(256, 2)
gates_kernel(const float* __restrict__ observed,
             const float* __restrict__ W_emb, const float* __restrict__ b_emb,
             const float* __restrict__ W_out, const float* __restrict__ b_out,
             float* __restrict__ out, int s)
{
    extern __shared__ char smraw[];
    const uint32_t sm0  = smem_u32(smraw);
    const uint32_t base = (sm0 + 1023) & ~1023u;
    const uint32_t pad  = base - sm0;
    const uint32_t Soff[2] = {base, base + STAGE_B};

    const int tid  = threadIdx.x;
    const int wid  = tid >> 5;
    const int lane = tid & 31;
    const int wm   = wid >> 2;      // 0..1 : warp M position (64 rows each)
    const int wn   = wid & 3;       // 0..3 : warp N position (32 cols each)
    const int bn   = blockIdx.x;    // 0..31 (permuted gate-col tile)
    const int bm   = blockIdx.y;    // 0..31 (batch tile)

    const __nv_bfloat16* Xhi_r = g_Xh[s & 1];
    const __nv_bfloat16* Xlo_r = g_Xl[s & 1];
    __nv_bfloat16* Xhi_w = g_Xh[(s + 1) & 1];
    __nv_bfloat16* Xlo_w = g_Xl[(s + 1) & 1];

    // kick off W chunk 0 ASAP (no A cp.async for chunks 0/1)
    load_chunk(Soff[0], Xhi_r, Xlo_r, bm, bn, 0, tid);

    float* bias_s = (float*)(smraw + pad + SBIAS);
    if (tid < TN) bias_s[tid] = g_bp[bn * TN + tid];
    float* wsout = (float*)(smraw + pad + SWOUT);
    if (tid < 160) wsout[tid] = W_out[(tid >> 5) * HID + bn * 32 + (tid & 31)];

    // ---- prologue A: finish out[s-1] (scratch partial reduction) ----
    float* out01 = (float*)(smraw + pad + SOUT01);
    if (s > 0) {
        if (s >= NOBS || bn == 0) {
            const int r_lo = tid & 127, o_sel = tid >> 7;   // (row, o in {0,1})
            const int grow = bm * TM + r_lo;
            float a_ = b_out[o_sel];
            #pragma unroll 8
            for (int q2 = 0; q2 < 32; ++q2) a_ += g_osc[q2][o_sel][grow];
            out01[o_sel * 128 + r_lo] = a_;
            if (bn == 0) {
                out[(size_t)(s - 1) * BATCH * 5 + (size_t)grow * 5 + o_sel] = a_;
                if (tid < 128) {
                    #pragma unroll
                    for (int o2 = 2; o2 < 5; ++o2) {
                        float b_ = b_out[o2];
                        #pragma unroll 8
                        for (int q2 = 0; q2 < 32; ++q2) b_ += g_osc[q2][o2][grow];
                        out[(size_t)(s - 1) * BATCH * 5 + (size_t)grow * 5 + o2] = b_;
                    }
                }
            }
        }
        __syncthreads();
    }

    // ---- prologue B: embedding -> swizzled A slots of stages 0 (e<32) / 1 (e>=32) ----
    {
        const int rloc = tid >> 1, eh = tid & 1;
        const int grow = bm * TM + rloc;
        float d0, d1;
        if (s < NOBS) {
            const float* o1 = observed + (size_t)(s + 1) * BATCH * 2 + (size_t)grow * 2;
            const float* o0 = observed + (size_t)s       * BATCH * 2 + (size_t)grow * 2;
            d0 = o1[0] - o0[0];
            d1 = o1[1] - o0[1];
        } else {
            d0 = out01[rloc];
            d1 = out01[128 + rloc];
        }
        const uint32_t ahi = Soff[eh] + T_AHI;
        const uint32_t alo = Soff[eh] + T_ALO;
        #pragma unroll
        for (int p = 0; p < 16; ++p) {
            const int e0 = eh * 32 + p * 2;
            float v0 = fmaxf(fmaf(W_emb[e0 * 2],     d0,
                           fmaf(W_emb[e0 * 2 + 1], d1, b_emb[e0])), 0.0f);
            float v1 = fmaxf(fmaf(W_emb[e0 * 2 + 2], d0,
                           fmaf(W_emb[e0 * 2 + 3], d1, b_emb[e0 + 1])), 0.0f);
            __nv_bfloat16 h0 = __float2bfloat16(v0), h1 = __float2bfloat16(v1);
            uint32_t whi = (uint32_t)__bfloat16_as_ushort(h0)
                         | ((uint32_t)__bfloat16_as_ushort(h1) << 16);
            uint32_t wlo = (uint32_t)__bfloat16_as_ushort(__float2bfloat16(v0 - __bfloat162float(h0)))
                         | ((uint32_t)__bfloat16_as_ushort(__float2bfloat16(v1 - __bfloat162float(h1))) << 16);
            const uint32_t o = swz64((uint32_t)(rloc * 64 + p * 4));
            sts32(ahi + o, whi);
            sts32(alo + o, wlo);
        }
    }

    // ---- mainloop: chunk-major, 3 products per chunk ----
    float acc[4][4][4];
    #pragma unroll
    for (int mt = 0; mt < 4; ++mt)
        #pragma unroll
        for (int nt = 0; nt < 4; ++nt)
            #pragma unroll
            for (int v = 0; v < 4; ++v) acc[mt][nt][v] = 0.0f;

    const int niter = (s == 0) ? 2 : NCHUNK;   // step 0: h==0, emb chunks only
    const int lrow  = lane & 15;
    const int lhalf = (lane >> 4) * 16;

    for (int it = 0; it < niter; ++it) {
        const int b = it & 1, nb = b ^ 1;
        if (it + 1 < niter) {
            load_chunk(Soff[nb], Xhi_r, Xlo_r, bm, bn, it + 1, tid);
            asm volatile("cp.async.wait_group 1;" ::: "memory");
        } else {
            asm volatile("cp.async.wait_group 0;" ::: "memory");
        }
        __syncthreads();

        const uint32_t st = Soff[b];
        #pragma unroll
        for (int kk = 0; kk < 2; ++kk) {
            uint32_t bhi[2][4], blo[2][4];
            #pragma unroll
            for (int nt2 = 0; nt2 < 2; ++nt2) {
                const uint32_t boff = swz64((uint32_t)((wn * 32 + nt2 * 16 + lrow) * 64 + kk * 32 + lhalf));
                ldmat4(bhi[nt2], st + T_WHI + boff);
                ldmat4(blo[nt2], st + T_WLO + boff);
            }
            #pragma unroll
            for (int mt = 0; mt < 4; ++mt) {
                const uint32_t aoff = swz64((uint32_t)((wm * 64 + mt * 16 + lrow) * 64 + kk * 32 + lhalf));
                uint32_t ahi[4], alo[4];
                ldmat4(ahi, st + T_AHI + aoff);
                ldmat4(alo, st + T_ALO + aoff);
                #pragma unroll
                for (int nt = 0; nt < 4; ++nt) {
                    const uint32_t* bf = bhi[nt >> 1];
                    uint32_t b0 = (nt & 1) ? bf[1] : bf[0];
                    uint32_t b1 = (nt & 1) ? bf[3] : bf[2];
                    mma16816(acc[mt][nt], ahi, b0, b1);
                    mma16816(acc[mt][nt], alo, b0, b1);
                    const uint32_t* bl = blo[nt >> 1];
                    uint32_t c0 = (nt & 1) ? bl[1] : bl[0];
                    uint32_t c1 = (nt & 1) ? bl[3] : bl[2];
                    mma16816(acc[mt][nt], ahi, c0, c1);
                }
            }
        }
        __syncthreads();
    }

    // ------- dump accumulators to smem (gbuf overlays stage buffers) -------
    float* gbuf = (float*)(smraw + pad);
    #pragma unroll
    for (int mt = 0; mt < 4; ++mt)
        #pragma unroll
        for (int nt = 0; nt < 4; ++nt) {
            int r0 = wm * 64 + mt * 16 + (lane >> 2);
            int c  = wn * 32 + nt * 8 + (lane & 3) * 2;
            *(float2*)&gbuf[r0 * GB_STRIDE + c]       = make_float2(acc[mt][nt][0], acc[mt][nt][1]);
            *(float2*)&gbuf[(r0 + 8) * GB_STRIDE + c] = make_float2(acc[mt][nt][2], acc[mt][nt][3]);
        }
    __syncthreads();

    // ------- epilogue: LSTM cell + h store; hn staged in smem -------
    float* hbuf = (float*)(smraw + pad + SHBUF);
    #pragma unroll 1
    for (int u = 0; u < 16; ++u) {
        int idx = tid + 256 * u;       // warp wid handles m = wid + 8u, j = lane
        int m = idx >> 5, j = idx & 31;
        int row = bm * TM + m;
        int jglob = bn * 32 + j;
        const float* gp = &gbuf[m * GB_STRIDE + j * 4];
        float gi = gp[0] + bias_s[j * 4 + 0];
        float gf = gp[1] + bias_s[j * 4 + 1];
        float gg = gp[2] + bias_s[j * 4 + 2];
        float go = gp[3] + bias_s[j * 4 + 3];
        float xi = sigf(gi), xf = sigf(gf);
        float xg = tanh_f(gg), xo = sigf(go);
        size_t ci = (size_t)row * HID + jglob;
        float cold = (s > 0) ? g_c[ci] : 0.0f;
        float cn = fmaf(xf, cold, xi * xg);
        g_c[ci] = cn;
        float hn = xo * tanh_f(cn);
        __nv_bfloat16 hb = __float2bfloat16(hn);
        Xhi_w[ci] = hb;
        Xlo_w[ci] = __float2bfloat16(hn - __bfloat162float(hb));
        hbuf[m * HB_STRIDE + j] = hn;
    }
    __syncthreads();

    // ------- out_proj partials: 128 threads, one row each (smem reduce) -------
    if (tid < 128) {
        const int row = bm * TM + tid;
        const float* hr = &hbuf[tid * HB_STRIDE];
        float a0 = 0.f, a1 = 0.f, a2 = 0.f, a3 = 0.f, a4 = 0.f;
        #pragma unroll
        for (int j = 0; j < 32; ++j) {
            float h = hr[j];
            a0 = fmaf(h, wsout[j],       a0);
            a1 = fmaf(h, wsout[32 + j],  a1);
            a2 = fmaf(h, wsout[64 + j],  a2);
            a3 = fmaf(h, wsout[96 + j],  a3);
            a4 = fmaf(h, wsout[128 + j], a4);
        }
        g_osc[bn][0][row] = a0;
        g_osc[bn][1][row] = a1;
        g_osc[bn][2][row] = a2;
        g_osc[bn][3][row] = a3;
        g_osc[bn][4][row] = a4;
    }
}

// ---------------- final output row: reduce scratch partials for step 18 ----------------
extern "C" __global__ void __launch_bounds__(256)
reduce_out_kernel(const float* __restrict__ b_out, float* __restrict__ out, int s)
{
    int row = blockIdx.x * 256 + threadIdx.x;   // 0..4095
    #pragma unroll
    for (int o = 0; o < 5; ++o) {
        float a = b_out[o];
        #pragma unroll 8
        for (int q = 0; q < 32; ++q) a += g_osc[q][o][row];
        out[(size_t)s * BATCH * 5 + (size_t)row * 5 + o] = a;
    }
}

extern "C" void kernel_launch(void* const* d_in, const int* in_sizes, int n_in,
                              void* d_out, int out_size)
{
    const float* observed = (const float*)d_in[0];
    const float* W_emb    = (const float*)d_in[1];
    const float* b_emb    = (const float*)d_in[2];
    const float* W_ih     = (const float*)d_in[3];
    const float* b_ih     = (const float*)d_in[4];
    const float* W_hh     = (const float*)d_in[5];
    const float* b_hh     = (const float*)d_in[6];
    const float* W_out    = (const float*)d_in[7];
    const float* b_out    = (const float*)d_in[8];
    float* out = (float*)d_out;

    cudaFuncSetAttribute(gates_kernel, cudaFuncAttributeMaxDynamicSharedMemorySize, SMEM_BYTES);

    prep_kernel<<<(GROWS * KDIM) / 256, 256>>>(W_ih, b_ih, W_hh, b_hh);

    dim3 grid(GROWS / TN, BATCH / TM);   // (32, 32)
    for (int s = 0; s < NSTEPS; ++s) {
        gates_kernel<<<grid, 256, SMEM_BYTES>>>(observed, W_emb, b_emb,
                                                W_out, b_out, out, s);
    }
    reduce_out_kernel<<<BATCH / 256, 256>>>(b_out, out, NSTEPS - 1);
}

// round 17
// speedup vs baseline: 1.1220x; 1.0969x over previous
#include <cuda_runtime.h>
#include <cuda_bf16.h>
#include <math.h>
#include <stdint.h>

// Problem constants
#define BATCH   4096
#define HID     1024
#define EMBD    64
#define KDIM    1088          // EMBD + HID (W layout only; X holds h only)
#define NOBS    8
#define NSTEPS  19
#define GROWS   4096          // 4*HID gate rows

// GEMM tiling
#define TM      128           // batch rows per CTA
#define TN      128           // permuted gate cols per CTA = 32 hidden units x 4 gates
#define TKC     32            // K chunk (32 bf16 = 64B rows -> SW64 swizzle)
#define NCHUNK  34            // 2 emb chunks (smem-computed) + 32 h chunks

// smem: 3 stages x 4 tiles (Ahi, Alo, Whi, Wlo) x 8KB = 96KB
// gbuf (67584B) and hbuf (16896B) overlay the stage region after the GEMM.
#define STAGE_B 32768
#define T_AHI   0
#define T_ALO   8192
#define T_WHI   16384
#define T_WLO   24576
#define GB_STRIDE 132
#define SHBUF   67584         // overlay: 67584 + 16896 = 84480 < 98304
#define HB_STRIDE 33
#define SBIAS   98304         // 512B: permuted gate bias
#define SOUT01  98816         // 1024B: out[s-1][:,0:2] for this CTA's 128 rows
#define SWOUT   99840         // 640B: W_out[0:5][bn*32 .. bn*32+31]
#define SMEM_BYTES (100480 + 1024)

// ---------------- device state (allocation-free scratch) ----------------
// h double-buffered by STEP PARITY (race-free across CTAs/waves).
__device__ __nv_bfloat16 g_Xh[2][BATCH * HID];    // h hi
__device__ __nv_bfloat16 g_Xl[2][BATCH * HID];    // h lo residual
__device__ __nv_bfloat16 g_Wphi[GROWS * KDIM];    // permuted [W_ih|W_hh] hi
__device__ __nv_bfloat16 g_Wplo[GROWS * KDIM];    // lo residual
__device__ float         g_bp[GROWS];             // permuted b_ih+b_hh
__device__ float         g_c[BATCH * HID];        // cell state (fp32)
__device__ float         g_osc[32][5][BATCH];     // out_proj partials [bn][o][row]

// ---------------- helpers ----------------
__device__ __forceinline__ uint32_t smem_u32(const void* p) {
    uint32_t a;
    asm("{ .reg .u64 t; cvta.to.shared.u64 t, %1; cvt.u32.u64 %0, t; }" : "=r"(a) : "l"(p));
    return a;
}
__device__ __forceinline__ void cp16(uint32_t dst, const void* src) {
    asm volatile("cp.async.cg.shared.global [%0], [%1], 16;" :: "r"(dst), "l"(src));
}
#define CP_COMMIT() asm volatile("cp.async.commit_group;" ::: "memory")
__device__ __forceinline__ uint32_t swz64(uint32_t off) { return off ^ ((off >> 3) & 0x30); }
__device__ __forceinline__ void sts32(uint32_t addr, uint32_t v) {
    asm volatile("st.shared.b32 [%0], %1;" :: "r"(addr), "r"(v));
}
__device__ __forceinline__ void ldmat4(uint32_t* r, uint32_t addr) {
    asm volatile("ldmatrix.sync.aligned.m8n8.x4.shared.b16 {%0,%1,%2,%3}, [%4];"
        : "=r"(r[0]), "=r"(r[1]), "=r"(r[2]), "=r"(r[3]) : "r"(addr));
}
__device__ __forceinline__ void mma16816(float* c, const uint32_t* a, uint32_t b0, uint32_t b1) {
    asm volatile("mma.sync.aligned.m16n8k16.row.col.f32.bf16.bf16.f32 "
        "{%0,%1,%2,%3}, {%4,%5,%6,%7}, {%8,%9}, {%0,%1,%2,%3};"
        : "+f"(c[0]), "+f"(c[1]), "+f"(c[2]), "+f"(c[3])
        : "r"(a[0]), "r"(a[1]), "r"(a[2]), "r"(a[3]), "r"(b0), "r"(b1));
}

__device__ __forceinline__ float sigf(float x) {
    return __fdividef(1.0f, 1.0f + __expf(-x));
}
__device__ __forceinline__ float tanh_f(float x) {
    return fmaf(2.0f, sigf(2.0f * x), -1.0f);
}

// ---------------- one-time prep: permute+split W, combine biases ----------------
extern "C" __global__ void __launch_bounds__(256)
prep_kernel(const float* __restrict__ W_ih, const float* __restrict__ b_ih,
            const float* __restrict__ W_hh, const float* __restrict__ b_hh)
{
    int idx = blockIdx.x * 256 + threadIdx.x;       // 0 .. GROWS*KDIM
    int ro = idx / KDIM, k = idx - ro * KDIM;
    int j = ro >> 2, q = ro & 3;                    // ro = j*4 + gate
    int orig = q * HID + j;
    float v = (k < EMBD) ? W_ih[(size_t)orig * EMBD + k]
                         : W_hh[(size_t)orig * HID + (k - EMBD)];
    __nv_bfloat16 hi = __float2bfloat16(v);
    g_Wphi[idx] = hi;
    g_Wplo[idx] = __float2bfloat16(v - __bfloat162float(hi));
    if (k == 0) g_bp[ro] = b_ih[orig] + b_hh[orig];
}

// ---------------- fused per-step kernel ----------------
// prologue: reduce out[s-1] partials (d_out write + predictive feedback) + emb
// mainloop: 3-stage cp.async pipeline, 1 barrier/iter, 3-pass split-bf16 GEMM
// epilogue: LSTM cell + h hi/lo store; out_proj partials via smem hbuf
extern "C" __global__ void __launch_bounds__(256, 2)
gates_kernel(const float* __restrict__ observed,
             const float* __restrict__ W_emb, const float* __restrict__ b_emb,
             const float* __restrict__ W_out, const float* __restrict__ b_out,
             float* __restrict__ out, int s)
{
    extern __shared__ char smraw[];
    const uint32_t sm0  = smem_u32(smraw);
    const uint32_t base = (sm0 + 1023) & ~1023u;
    const uint32_t pad  = base - sm0;
    const uint32_t Soff[3] = {base, base + STAGE_B, base + 2 * STAGE_B};

    const int tid  = threadIdx.x;
    const int wid  = tid >> 5;
    const int lane = tid & 31;
    const int wm   = wid >> 2;      // 0..1 : warp M position (64 rows each)
    const int wn   = wid & 3;       // 0..3 : warp N position (32 cols each)
    const int bn   = blockIdx.x;    // 0..31 (permuted gate-col tile)
    const int bm   = blockIdx.y;    // 0..31 (batch tile)

    const __nv_bfloat16* Xhi_r = g_Xh[s & 1];
    const __nv_bfloat16* Xlo_r = g_Xl[s & 1];
    __nv_bfloat16* Xhi_w = g_Xh[(s + 1) & 1];
    __nv_bfloat16* Xlo_w = g_Xl[(s + 1) & 1];

    // ---- loader state (per-thread, incremental) ----
    const int lr = tid >> 2, lq = tid & 3;         // 64 rows x 4 16B-quads
    const uint32_t so0 = swz64((uint32_t)(lr * 64 + lq * 16));
    const uint32_t so1 = swz64((uint32_t)((lr + 64) * 64 + lq * 16));
    const __nv_bfloat16* pwbase = g_Wphi + (size_t)(bn * TN + lr) * KDIM + lq * 8;
    const ptrdiff_t dW = g_Wplo - g_Wphi;

    // prologue: W-only loads for chunks 0 and 1 (A slots are smem-computed emb)
    {
        cp16(Soff[0] + T_WHI + so0, pwbase);
        cp16(Soff[0] + T_WHI + so1, pwbase + 64 * KDIM);
        cp16(Soff[0] + T_WLO + so0, pwbase + dW);
        cp16(Soff[0] + T_WLO + so1, pwbase + dW + 64 * KDIM);
        CP_COMMIT();
        cp16(Soff[1] + T_WHI + so0, pwbase + TKC);
        cp16(Soff[1] + T_WHI + so1, pwbase + TKC + 64 * KDIM);
        cp16(Soff[1] + T_WLO + so0, pwbase + dW + TKC);
        cp16(Soff[1] + T_WLO + so1, pwbase + dW + TKC + 64 * KDIM);
        CP_COMMIT();
    }
    // in-loop pointers start at chunk 2
    const __nv_bfloat16* pw0 = pwbase + 2 * TKC;
    const __nv_bfloat16* pa0 = Xhi_r + (size_t)(bm * TM + lr) * HID + lq * 8;
    const ptrdiff_t dX = Xlo_r - Xhi_r;

    float* bias_s = (float*)(smraw + pad + SBIAS);
    if (tid < TN) bias_s[tid] = g_bp[bn * TN + tid];
    float* wsout = (float*)(smraw + pad + SWOUT);
    if (tid < 160) wsout[tid] = W_out[(tid >> 5) * HID + bn * 32 + (tid & 31)];

    // ---- prologue A: finish out[s-1] (scratch partial reduction) ----
    float* out01 = (float*)(smraw + pad + SOUT01);
    if (s > 0) {
        if (s >= NOBS || bn == 0) {
            const int r_lo = tid & 127, o_sel = tid >> 7;   // (row, o in {0,1})
            const int grow = bm * TM + r_lo;
            float a_ = b_out[o_sel];
            #pragma unroll 8
            for (int q2 = 0; q2 < 32; ++q2) a_ += g_osc[q2][o_sel][grow];
            out01[o_sel * 128 + r_lo] = a_;
            if (bn == 0) {
                out[(size_t)(s - 1) * BATCH * 5 + (size_t)grow * 5 + o_sel] = a_;
                if (tid < 128) {
                    #pragma unroll
                    for (int o2 = 2; o2 < 5; ++o2) {
                        float b_ = b_out[o2];
                        #pragma unroll 8
                        for (int q2 = 0; q2 < 32; ++q2) b_ += g_osc[q2][o2][grow];
                        out[(size_t)(s - 1) * BATCH * 5 + (size_t)grow * 5 + o2] = b_;
                    }
                }
            }
        }
        __syncthreads();
    }

    // ---- prologue B: embedding -> swizzled A slots of stages 0 (e<32) / 1 (e>=32) ----
    {
        const int rloc = tid >> 1, eh = tid & 1;
        const int grow = bm * TM + rloc;
        float d0, d1;
        if (s < NOBS) {
            const float* o1 = observed + (size_t)(s + 1) * BATCH * 2 + (size_t)grow * 2;
            const float* o0 = observed + (size_t)s       * BATCH * 2 + (size_t)grow * 2;
            d0 = o1[0] - o0[0];
            d1 = o1[1] - o0[1];
        } else {
            d0 = out01[rloc];
            d1 = out01[128 + rloc];
        }
        const uint32_t ahi = Soff[eh] + T_AHI;
        const uint32_t alo = Soff[eh] + T_ALO;
        #pragma unroll
        for (int p = 0; p < 16; ++p) {
            const int e0 = eh * 32 + p * 2;
            float v0 = fmaxf(fmaf(W_emb[e0 * 2],     d0,
                           fmaf(W_emb[e0 * 2 + 1], d1, b_emb[e0])), 0.0f);
            float v1 = fmaxf(fmaf(W_emb[e0 * 2 + 2], d0,
                           fmaf(W_emb[e0 * 2 + 3], d1, b_emb[e0 + 1])), 0.0f);
            __nv_bfloat16 h0 = __float2bfloat16(v0), h1 = __float2bfloat16(v1);
            uint32_t whi = (uint32_t)__bfloat16_as_ushort(h0)
                         | ((uint32_t)__bfloat16_as_ushort(h1) << 16);
            uint32_t wlo = (uint32_t)__bfloat16_as_ushort(__float2bfloat16(v0 - __bfloat162float(h0)))
                         | ((uint32_t)__bfloat16_as_ushort(__float2bfloat16(v1 - __bfloat162float(h1))) << 16);
            const uint32_t o = swz64((uint32_t)(rloc * 64 + p * 4));
            sts32(ahi + o, whi);
            sts32(alo + o, wlo);
        }
    }

    // ---- mainloop: 3-stage pipeline, 1 barrier/iter, 3 products per chunk ----
    float acc[4][4][4];
    #pragma unroll
    for (int mt = 0; mt < 4; ++mt)
        #pragma unroll
        for (int nt = 0; nt < 4; ++nt)
            #pragma unroll
            for (int v = 0; v < 4; ++v) acc[mt][nt][v] = 0.0f;

    const int niter = (s == 0) ? 2 : NCHUNK;   // step 0: h==0, emb chunks only
    const int lrow  = lane & 15;
    const int lhalf = (lane >> 4) * 16;

    int rs = 0;
    for (int it = 0; it < niter; ++it) {
        asm volatile("cp.async.wait_group 1;" ::: "memory");
        __syncthreads();    // data for chunk it visible to all; stage rs-1 free for reuse

        const uint32_t st = Soff[rs];
        #pragma unroll
        for (int kk = 0; kk < 2; ++kk) {
            uint32_t bhi[2][4], blo[2][4];
            #pragma unroll
            for (int nt2 = 0; nt2 < 2; ++nt2) {
                const uint32_t boff = swz64((uint32_t)((wn * 32 + nt2 * 16 + lrow) * 64 + kk * 32 + lhalf));
                ldmat4(bhi[nt2], st + T_WHI + boff);
                ldmat4(blo[nt2], st + T_WLO + boff);
            }
            #pragma unroll
            for (int mt = 0; mt < 4; ++mt) {
                const uint32_t aoff = swz64((uint32_t)((wm * 64 + mt * 16 + lrow) * 64 + kk * 32 + lhalf));
                uint32_t ahi[4], alo[4];
                ldmat4(ahi, st + T_AHI + aoff);
                ldmat4(alo, st + T_ALO + aoff);
                #pragma unroll
                for (int nt = 0; nt < 4; ++nt) {
                    const uint32_t* bf = bhi[nt >> 1];
                    uint32_t b0 = (nt & 1) ? bf[1] : bf[0];
                    uint32_t b1 = (nt & 1) ? bf[3] : bf[2];
                    mma16816(acc[mt][nt], ahi, b0, b1);
                    mma16816(acc[mt][nt], alo, b0, b1);
                    const uint32_t* bl = blo[nt >> 1];
                    uint32_t c0 = (nt & 1) ? bl[1] : bl[0];
                    uint32_t c1 = (nt & 1) ? bl[3] : bl[2];
                    mma16816(acc[mt][nt], ahi, c0, c1);
                }
            }
        }

        // issue chunk it+2 into stage (rs+2)%3 (read in it-1; freed by this iter's barrier)
        if (it + 2 < niter) {
            const uint32_t wg = Soff[rs == 0 ? 2 : rs - 1];
            cp16(wg + T_AHI + so0, pa0);
            cp16(wg + T_AHI + so1, pa0 + 64 * HID);
            cp16(wg + T_ALO + so0, pa0 + dX);
            cp16(wg + T_ALO + so1, pa0 + dX + 64 * HID);
            cp16(wg + T_WHI + so0, pw0);
            cp16(wg + T_WHI + so1, pw0 + 64 * KDIM);
            cp16(wg + T_WLO + so0, pw0 + dW);
            cp16(wg + T_WLO + so1, pw0 + dW + 64 * KDIM);
            pa0 += TKC;
            pw0 += TKC;
        }
        CP_COMMIT();        // always commit so wait_group counts stay aligned

        if (++rs == 3) rs = 0;
    }
    __syncthreads();        // all mma reads done before gbuf/hbuf overlay stages

    // ------- dump accumulators to smem (gbuf overlays stage buffers) -------
    float* gbuf = (float*)(smraw + pad);
    #pragma unroll
    for (int mt = 0; mt < 4; ++mt)
        #pragma unroll
        for (int nt = 0; nt < 4; ++nt) {
            int r0 = wm * 64 + mt * 16 + (lane >> 2);
            int c  = wn * 32 + nt * 8 + (lane & 3) * 2;
            *(float2*)&gbuf[r0 * GB_STRIDE + c]       = make_float2(acc[mt][nt][0], acc[mt][nt][1]);
            *(float2*)&gbuf[(r0 + 8) * GB_STRIDE + c] = make_float2(acc[mt][nt][2], acc[mt][nt][3]);
        }
    __syncthreads();

    // ------- epilogue: LSTM cell + h store; hn staged in smem -------
    float* hbuf = (float*)(smraw + pad + SHBUF);
    #pragma unroll 1
    for (int u = 0; u < 16; ++u) {
        int idx = tid + 256 * u;
        int m = idx >> 5, j = idx & 31;
        int row = bm * TM + m;
        int jglob = bn * 32 + j;
        const float* gp = &gbuf[m * GB_STRIDE + j * 4];
        float gi = gp[0] + bias_s[j * 4 + 0];
        float gf = gp[1] + bias_s[j * 4 + 1];
        float gg = gp[2] + bias_s[j * 4 + 2];
        float go = gp[3] + bias_s[j * 4 + 3];
        float xi = sigf(gi), xf = sigf(gf);
        float xg = tanh_f(gg), xo = sigf(go);
        size_t ci = (size_t)row * HID + jglob;
        float cold = (s > 0) ? g_c[ci] : 0.0f;
        float cn = fmaf(xf, cold, xi * xg);
        g_c[ci] = cn;
        float hn = xo * tanh_f(cn);
        __nv_bfloat16 hb = __float2bfloat16(hn);
        Xhi_w[ci] = hb;
        Xlo_w[ci] = __float2bfloat16(hn - __bfloat162float(hb));
        hbuf[m * HB_STRIDE + j] = hn;
    }
    __syncthreads();

    // ------- out_proj partials: 128 threads, one row each (smem reduce) -------
    if (tid < 128) {
        const int row = bm * TM + tid;
        const float* hr = &hbuf[tid * HB_STRIDE];
        float a0 = 0.f, a1 = 0.f, a2 = 0.f, a3 = 0.f, a4 = 0.f;
        #pragma unroll
        for (int j = 0; j < 32; ++j) {
            float h = hr[j];
            a0 = fmaf(h, wsout[j],       a0);
            a1 = fmaf(h, wsout[32 + j],  a1);
            a2 = fmaf(h, wsout[64 + j],  a2);
            a3 = fmaf(h, wsout[96 + j],  a3);
            a4 = fmaf(h, wsout[128 + j], a4);
        }
        g_osc[bn][0][row] = a0;
        g_osc[bn][1][row] = a1;
        g_osc[bn][2][row] = a2;
        g_osc[bn][3][row] = a3;
        g_osc[bn][4][row] = a4;
    }
}

// ---------------- final output row: reduce scratch partials for step 18 ----------------
extern "C" __global__ void __launch_bounds__(256)
reduce_out_kernel(const float* __restrict__ b_out, float* __restrict__ out, int s)
{
    int row = blockIdx.x * 256 + threadIdx.x;   // 0..4095
    #pragma unroll
    for (int o = 0; o < 5; ++o) {
        float a = b_out[o];
        #pragma unroll 8
        for (int q = 0; q < 32; ++q) a += g_osc[q][o][row];
        out[(size_t)s * BATCH * 5 + (size_t)row * 5 + o] = a;
    }
}

extern "C" void kernel_launch(void* const* d_in, const int* in_sizes, int n_in,
                              void* d_out, int out_size)
{
    const float* observed = (const float*)d_in[0];
    const float* W_emb    = (const float*)d_in[1];
    const float* b_emb    = (const float*)d_in[2];
    const float* W_ih     = (const float*)d_in[3];
    const float* b_ih     = (const float*)d_in[4];
    const float* W_hh     = (const float*)d_in[5];
    const float* b_hh     = (const float*)d_in[6];
    const float* W_out    = (const float*)d_in[7];
    const float* b_out    = (const float*)d_in[8];
    float* out = (float*)d_out;

    cudaFuncSetAttribute(gates_kernel, cudaFuncAttributeMaxDynamicSharedMemorySize, SMEM_BYTES);

    prep_kernel<<<(GROWS * KDIM) / 256, 256>>>(W_ih, b_ih, W_hh, b_hh);

    dim3 grid(GROWS / TN, BATCH / TM);   // (32, 32)
    for (int s = 0; s < NSTEPS; ++s) {
        gates_kernel<<<grid, 256, SMEM_BYTES>>>(observed, W_emb, b_emb,
                                                W_out, b_out, out, s);
    }
    reduce_out_kernel<<<BATCH / 256, 256>>>(b_out, out, NSTEPS - 1);
}